// round 7
// baseline (speedup 1.0000x reference)
#include <cuda_runtime.h>
#include <cuda_fp16.h>
#include <cstdint>

#define BATCH   32768
#define NUM_IN  256
#define NUM_HID 512
#define NUM_OUT 64
#define M_NODES 576
#define N_NODES 832
#define KFAN    32
#define COLS    64             // batch columns per block (32 half2 words)
#define WPN     32             // u32 words per node row
#define THREADS 512            // 16 warps
#define SLOTS   32             // nodes per round (2 per warp, same level)
#define RSTRIDE 1600           // words/round: 512 src16 + 1024 w + 32 bias + 32 tgt
#define RMAX    576
#define DUMMY   576            // dummy pred index, level pinned 0

// round-major param blob, per round r at r*RSTRIDE:
//   [0..512)      src16: two u16 (pred*WPN) word-offsets per u32  (slot*16 + j)
//   [512..1536)   w     (512 + slot*32 + k)
//   [1536..1568)  bias per slot
//   [1568..1600)  target word-offset (tgt_row*WPN) per slot, -1 = dummy
__device__ float g_blob[(size_t)RMAX * RSTRIDE];
__device__ int   g_sched[RMAX * SLOTS];
__device__ int   g_nrounds;

// ---------------------------------------------------------------------------
// Kernel A: ASAP levels via in-place Jacobi (monotone, converges in depth
// passes), one fused barrier per pass; then counting-sort into 32-slot rounds.
// ---------------------------------------------------------------------------
__global__ __launch_bounds__(M_NODES)
void schedule_kernel(const int* __restrict__ src) {
    __shared__ int lev[DUMMY + 1];        // lev[DUMMY] pinned 0
    __shared__ int cnt[M_NODES + 1];
    __shared__ int rbase[M_NODES + 1];
    __shared__ int pos[M_NODES + 1];
    __shared__ int lmax, R_sh;

    const int t = threadIdx.x;

    int p[KFAN];
    #pragma unroll
    for (int k = 0; k < KFAN; k++) {
        int s = src[t * KFAN + k];
        p[k] = (s >= NUM_IN) ? (s - NUM_IN) : DUMMY;
    }
    lev[t] = 0;
    if (t == 0) { lev[DUMMY] = 0; lmax = 0; }
    for (int i = t; i <= M_NODES; i += M_NODES) { cnt[i] = 0; pos[i] = 0; }
    __syncthreads();

    // Jacobi fixpoint: levels only increase; stable pass => done.
    for (int pass = 0; pass < M_NODES; pass++) {
        int m = 0;
        #pragma unroll
        for (int k = 0; k < KFAN; k++) {
            int l = lev[p[k]];
            m = (l > m) ? l : m;
        }
        int ch = (m + 1 != lev[t]);
        if (ch) lev[t] = m + 1;
        if (!__syncthreads_or(ch)) break;
    }

    atomicAdd(&cnt[lev[t]], 1);
    atomicMax(&lmax, lev[t]);
    __syncthreads();

    if (t == 0) {
        int r = 0;
        for (int L = 1; L <= lmax; L++) { rbase[L] = r; r += (cnt[L] + SLOTS - 1) >> 5; }
        R_sh = r;
        g_nrounds = r;
    }
    __syncthreads();

    for (int i = t; i < R_sh * SLOTS; i += M_NODES) g_sched[i] = -1;
    __syncthreads();

    {
        int L = lev[t];
        int q = atomicAdd(&pos[L], 1);
        g_sched[(rbase[L] + (q >> 5)) * SLOTS + (q & 31)] = t;
    }
}

// ---------------------------------------------------------------------------
// Kernel B: grid-parallel blob fill, one block per (used) round.
// ---------------------------------------------------------------------------
__global__ __launch_bounds__(256)
void blob_fill_kernel(const int* __restrict__ src,
                      const float* __restrict__ w,
                      const float* __restrict__ bias) {
    const int r = blockIdx.x;
    if (r >= g_nrounds) return;
    float* Pr = g_blob + (size_t)r * RSTRIDE;
    const int tid = threadIdx.x;

    // src16: 512 words, premultiplied (pred * WPN) offsets
    #pragma unroll
    for (int u = 0; u < 2; u++) {
        int q = tid + u * 256;
        int slot = q >> 4, j = q & 15;
        int nd = g_sched[r * SLOTS + slot];
        unsigned v = 0;
        if (nd >= 0) {
            unsigned a = (unsigned)src[nd * KFAN + 2 * j] * WPN;
            unsigned b = (unsigned)src[nd * KFAN + 2 * j + 1] * WPN;
            v = (a & 0xFFFFu) | (b << 16);
        }
        ((unsigned*)Pr)[slot * 16 + j] = v;
    }
    // w: 1024 words
    #pragma unroll
    for (int u = 0; u < 4; u++) {
        int q = tid + u * 256;
        int slot = q >> 5, k = q & 31;
        int nd = g_sched[r * SLOTS + slot];
        Pr[512 + slot * 32 + k] = (nd >= 0) ? w[nd * KFAN + k] : 0.0f;
    }
    // bias + target
    if (tid < SLOTS) {
        int nd = g_sched[r * SLOTS + tid];
        Pr[1536 + tid] = (nd >= 0) ? bias[nd] : 0.0f;
        ((int*)Pr)[1568 + tid] = (nd >= 0) ? (NUM_IN + nd) * WPN : -1;
    }
}

// ---------------------------------------------------------------------------
// Main kernel: 512 blocks x 512 threads, 2 blocks/SM. State half2-packed in
// SMEM; params read straight from global via uniform __ldg (L1-resident).
// 32 same-level nodes per round (2 per warp), one barrier per round.
// ---------------------------------------------------------------------------
#define ST_WORDS    (N_NODES * WPN)                // 26624 u32
#define STAGE_WORDS 2112                           // 64x33 f32 transpose staging
#define TOTAL_WORDS (ST_WORDS + STAGE_WORDS)       // 28736 -> 114944 B

extern __shared__ float smem_f[];

__global__ __launch_bounds__(THREADS, 2)
void neat_main_kernel(const float* __restrict__ x,
                      float* __restrict__ out) {
    uint32_t* st   = (uint32_t*)smem_f;            // [N_NODES][WPN] half2 words
    float*   stage = smem_f + ST_WORDS;

    const int tid  = threadIdx.x;
    const int wid  = tid >> 5;
    const int lane = tid & 31;
    const int b0   = blockIdx.x * COLS;
    const int R    = g_nrounds;

    // ---- input: x[b][n] f32 -> st[n] half2-packed; 8 chunks of 32 inputs ----
    for (int ch = 0; ch < 8; ch++) {
        const int nc0 = ch * 32;
        __syncthreads();
        #pragma unroll
        for (int i = 0; i < 4; i++) {
            int idx = tid + i * THREADS;           // 2048 = 64 rows x 32 cols
            int row = idx >> 5, c = idx & 31;
            stage[row * 33 + c] = x[(size_t)(b0 + row) * NUM_IN + nc0 + c];
        }
        __syncthreads();
        #pragma unroll
        for (int i = 0; i < 2; i++) {
            int idx = tid + i * THREADS;           // 1024 = 32 nodes x 32 words
            int n = idx >> 5, wc = idx & 31;
            float lo = stage[(2 * wc) * 33 + n];
            float hi = stage[(2 * wc + 1) * 33 + n];
            __half2 h = __floats2half2_rn(lo, hi);
            st[(nc0 + n) * WPN + wc] = *(uint32_t*)&h;
        }
    }
    __syncthreads();

    uint32_t* stc = st + lane;                     // lane owns cols (2l, 2l+1)

    // ---- main rounds ----
    for (int r = 0; r < R; r++) {
        const float* Pr = g_blob + (size_t)r * RSTRIDE;

        #pragma unroll
        for (int dup = 0; dup < 2; dup++) {
            const int slot = wid + dup * 16;
            const int tgt  = __ldg((const int*)Pr + 1568 + slot);
            if (tgt >= 0) {
                const uint2*  s2 = (const uint2*)((const unsigned*)Pr + slot * 16);
                const float4* w4p = (const float4*)(Pr + 512 + slot * 32);
                const float   bt  = __ldg(Pr + 1536 + slot);

                float ax = 0.f, ay = 0.f, bx = 0.f, by = 0.f;
                float cx = 0.f, cy = 0.f, dx = 0.f, dy = 0.f;
                #pragma unroll
                for (int q = 0; q < 8; q++) {
                    uint2  u  = __ldg(&s2[q]);       // 4 src offsets (uniform)
                    float4 w4 = __ldg(&w4p[q]);      // 4 weights (uniform)
                    uint32_t p0 = stc[u.x & 0xFFFFu];
                    uint32_t p1 = stc[u.x >> 16];
                    uint32_t p2 = stc[u.y & 0xFFFFu];
                    uint32_t p3 = stc[u.y >> 16];
                    float2 v0 = __half22float2(*(__half2*)&p0);
                    float2 v1 = __half22float2(*(__half2*)&p1);
                    float2 v2 = __half22float2(*(__half2*)&p2);
                    float2 v3 = __half22float2(*(__half2*)&p3);
                    ax = fmaf(v0.x, w4.x, ax);  ay = fmaf(v0.y, w4.x, ay);
                    bx = fmaf(v1.x, w4.y, bx);  by = fmaf(v1.y, w4.y, by);
                    cx = fmaf(v2.x, w4.z, cx);  cy = fmaf(v2.y, w4.z, cy);
                    dx = fmaf(v3.x, w4.w, dx);  dy = fmaf(v3.y, w4.w, dy);
                }
                float z0 = (ax + bx) + (cx + dx) + bt;
                float z1 = (ay + by) + (cy + dy) + bt;
                float o0 = __fdividef(1.0f, 1.0f + __expf(-z0));
                float o1 = __fdividef(1.0f, 1.0f + __expf(-z1));
                __half2 h = __floats2half2_rn(o0, o1);
                stc[tgt] = *(uint32_t*)&h;
            }
        }
        __syncthreads();
    }

    // ---- output: out[b][j] f32; 2 chunks of 32 output nodes ----
    for (int ch = 0; ch < 2; ch++) {
        const int j0 = ch * 32;
        __syncthreads();
        #pragma unroll
        for (int i = 0; i < 2; i++) {
            int idx = tid + i * THREADS;           // 1024 = 32 j x 32 words
            int j = idx >> 5, wc = idx & 31;
            uint32_t u = st[(NUM_IN + NUM_HID + j0 + j) * WPN + wc];
            float2 v = __half22float2(*(__half2*)&u);
            stage[(2 * wc) * 33 + j]     = v.x;
            stage[(2 * wc + 1) * 33 + j] = v.y;
        }
        __syncthreads();
        #pragma unroll
        for (int i = 0; i < 4; i++) {
            int idx = tid + i * THREADS;           // 2048 = 64 rows x 32 j
            int row = idx >> 5, j = idx & 31;
            out[(size_t)(b0 + row) * NUM_OUT + j0 + j] = stage[row * 33 + j];
        }
    }
}

// ---------------------------------------------------------------------------
extern "C" void kernel_launch(void* const* d_in, const int* in_sizes, int n_in,
                              void* d_out, int out_size) {
    const float* x    = (const float*)d_in[0];
    const float* w    = (const float*)d_in[1];
    const float* bias = (const float*)d_in[2];
    const int*   src  = (const int*)d_in[3];
    float* out = (float*)d_out;
    (void)in_sizes; (void)n_in; (void)out_size;

    cudaFuncSetAttribute(neat_main_kernel,
                         cudaFuncAttributeMaxDynamicSharedMemorySize,
                         TOTAL_WORDS * 4);

    schedule_kernel<<<1, M_NODES>>>(src);
    blob_fill_kernel<<<RMAX, 256>>>(src, w, bias);
    neat_main_kernel<<<BATCH / COLS, THREADS, TOTAL_WORDS * 4>>>(x, out);
}

// round 8
// speedup vs baseline: 1.1888x; 1.1888x over previous
#include <cuda_runtime.h>
#include <cuda_fp16.h>
#include <cstdint>

#define BATCH   32768
#define NUM_IN  256
#define NUM_HID 512
#define NUM_OUT 64
#define M_NODES 576
#define N_NODES 832
#define KFAN    32
#define COLS    128            // batch columns per block (64 half2 words/node)
#define WPN     64             // u32 words per node row
#define THREADS 1024           // 32 warps
#define SLOTS   32             // nodes per round (1 per warp)
#define RSTRIDE 1600           // words/round: 512 src16 + 1024 w + 32 bias + 32 tgt
#define RMAX    576
#define EDGES   (M_NODES * KFAN)

// round-major param blob, per round r at r*RSTRIDE:
//   [0..512)      src16: two u16 (pred*WPN) word-offsets per u32 (slot*16 + j)
//   [512..1536)   w     (512 + slot*32 + k)
//   [1536..1568)  bias per slot
//   [1568..1600)  target word-offset (tgt_row*WPN) per slot, -1 = dummy
__device__ float g_blob[(size_t)RMAX * RSTRIDE];
__device__ int   g_sched[RMAX * SLOTS];
__device__ int   g_rcnt[RMAX];
__device__ int   g_nrounds;

// ---------------------------------------------------------------------------
// Kernel A: Kahn greedy list scheduling. 1 block, 576 threads (one per node).
// O(1) readiness via indegree; successors decremented on schedule.
// 2 barriers per round, ~45 rounds.
// ---------------------------------------------------------------------------
__global__ __launch_bounds__(M_NODES)
void schedule_kernel(const int* __restrict__ src) {
    __shared__ unsigned short succ[EDGES];
    __shared__ int soff[M_NODES + 1];
    __shared__ int scnt[M_NODES];
    __shared__ int indeg[M_NODES];
    __shared__ int picked;

    const int t = threadIdx.x;
    const unsigned lane = t & 31;

    int p[KFAN]; int np = 0;
    #pragma unroll
    for (int k = 0; k < KFAN; k++) {
        int s = src[t * KFAN + k];
        if (s >= NUM_IN) p[np++] = s - NUM_IN;
    }
    indeg[t] = np;
    scnt[t] = 0;
    __syncthreads();
    for (int j = 0; j < np; j++) atomicAdd(&scnt[p[j]], 1);
    __syncthreads();
    if (t == 0) {
        int acc = 0;
        for (int i = 0; i < M_NODES; i++) { soff[i] = acc; acc += scnt[i]; }
        soff[M_NODES] = acc;
    }
    __syncthreads();
    scnt[t] = soff[t];                 // reuse as fill cursor
    __syncthreads();
    for (int j = 0; j < np; j++) {
        int pos = atomicAdd(&scnt[p[j]], 1);
        succ[pos] = (unsigned short)t;
    }

    int done = 0;
    for (int r = 0; r < RMAX; r++) {
        if (t == 0) picked = 0;
        __syncthreads();                           // (A): prev decrements drained
        bool ready = (!done && indeg[t] == 0);
        unsigned bal = __ballot_sync(0xFFFFFFFFu, ready);
        int base = 0;
        if (lane == 0 && bal) base = atomicAdd(&picked, __popc(bal));
        base = __shfl_sync(0xFFFFFFFFu, base, 0);
        int slot = -1;
        if (ready) {
            int q = base + __popc(bal & ((1u << lane) - 1u));
            if (q < SLOTS) slot = q;
        }
        __syncthreads();                           // (B): picked final
        int pk = picked;
        if (pk == 0) { if (t == 0) g_nrounds = r; return; }
        if (t == 0) g_rcnt[r] = (pk < SLOTS) ? pk : SLOTS;
        if (slot >= 0) {
            done = 1;
            g_sched[r * SLOTS + slot] = t;
            for (int j = soff[t]; j < soff[t + 1]; j++)
                atomicSub(&indeg[succ[j]], 1);
        }
    }
    if (t == 0) g_nrounds = RMAX;
}

// ---------------------------------------------------------------------------
// Kernel B: grid-parallel blob fill, one block per (used) round.
// ---------------------------------------------------------------------------
__global__ __launch_bounds__(256)
void blob_fill_kernel(const int* __restrict__ src,
                      const float* __restrict__ w,
                      const float* __restrict__ bias) {
    const int r = blockIdx.x;
    if (r >= g_nrounds) return;
    const int rc = g_rcnt[r];
    float* Pr = g_blob + (size_t)r * RSTRIDE;
    const int tid = threadIdx.x;

    // src16: 512 words, premultiplied (pred * WPN) offsets
    #pragma unroll
    for (int u = 0; u < 2; u++) {
        int q = tid + u * 256;
        int slot = q >> 4, j = q & 15;
        int nd = (slot < rc) ? g_sched[r * SLOTS + slot] : -1;
        unsigned v = 0;
        if (nd >= 0) {
            unsigned a = (unsigned)src[nd * KFAN + 2 * j] * WPN;
            unsigned b = (unsigned)src[nd * KFAN + 2 * j + 1] * WPN;
            v = (a & 0xFFFFu) | (b << 16);
        }
        ((unsigned*)Pr)[slot * 16 + j] = v;
    }
    // w: 1024 words
    #pragma unroll
    for (int u = 0; u < 4; u++) {
        int q = tid + u * 256;
        int slot = q >> 5, k = q & 31;
        int nd = (slot < rc) ? g_sched[r * SLOTS + slot] : -1;
        Pr[512 + slot * 32 + k] = (nd >= 0) ? w[nd * KFAN + k] : 0.0f;
    }
    // bias + target
    if (tid < SLOTS) {
        int nd = (tid < rc) ? g_sched[r * SLOTS + tid] : -1;
        Pr[1536 + tid] = (nd >= 0) ? bias[nd] : 0.0f;
        ((int*)Pr)[1568 + tid] = (nd >= 0) ? (NUM_IN + nd) * WPN : -1;
    }
}

// ---------------------------------------------------------------------------
// Main kernel: 256 blocks x 1024 threads, 1 block/SM. State half2-packed:
// st[n] has 64 u32 words (128 cols); lane owns words (2l, 2l+1) = 4 cols,
// gathered with one LDS.64. Params double-buffered in SMEM via cp.async.
// ---------------------------------------------------------------------------
#define ST_WORDS    (N_NODES * WPN)                // 53248 u32
#define STAGE_WORDS (2 * RSTRIDE)                  // 3200 (>= 128x17 staging)
#define TOTAL_WORDS (ST_WORDS + STAGE_WORDS)       // 56448 -> 225792 B

extern __shared__ float smem_f[];

__device__ __forceinline__ void cp16(void* sdst, const void* gsrc) {
    uint32_t s = (uint32_t)__cvta_generic_to_shared(sdst);
    asm volatile("cp.async.cg.shared.global [%0], [%1], 16;\n" :: "r"(s), "l"(gsrc));
}

__global__ __launch_bounds__(THREADS, 1)
void neat_main_kernel(const float* __restrict__ x,
                      float* __restrict__ out) {
    uint32_t* st   = (uint32_t*)smem_f;            // [N_NODES][WPN] half2 words
    float*   stage = smem_f + ST_WORDS;

    const int tid  = threadIdx.x;
    const int wid  = tid >> 5;
    const int lane = tid & 31;
    const int b0   = blockIdx.x * COLS;
    const int R    = g_nrounds;

    // ---- input: x[b][n] f32 -> st[n] half2-packed; 16 chunks of 16 inputs ----
    for (int ch = 0; ch < 16; ch++) {
        const int nc0 = ch * 16;
        __syncthreads();
        #pragma unroll
        for (int i = 0; i < 2; i++) {
            int idx = tid + i * THREADS;           // 2048 = 128 rows x 16 cols
            int row = idx >> 4, c = idx & 15;
            stage[row * 17 + c] = x[(size_t)(b0 + row) * NUM_IN + nc0 + c];
        }
        __syncthreads();
        {
            int n = tid >> 6, wc = tid & 63;       // 1024 = 16 nodes x 64 words
            float lo = stage[(2 * wc) * 17 + n];
            float hi = stage[(2 * wc + 1) * 17 + n];
            __half2 h = __floats2half2_rn(lo, hi);
            st[(nc0 + n) * WPN + wc] = *(uint32_t*)&h;
        }
    }
    __syncthreads();

    // ---- prefetch round 0 params ----
    if (tid < RSTRIDE / 4) cp16(stage + tid * 4, g_blob + tid * 4);
    asm volatile("cp.async.commit_group;\n");
    asm volatile("cp.async.wait_group 0;\n" ::: "memory");
    __syncthreads();

    uint32_t* stc = st + 2 * lane;                 // lane owns words (2l, 2l+1)

    // ---- main rounds: warp wid evaluates slot wid over 128 columns ----
    for (int r = 0; r < R; r++) {
        float* P  = stage + (r & 1) * RSTRIDE;
        float* Pn = stage + ((r + 1) & 1) * RSTRIDE;
        if (r + 1 < R && tid < RSTRIDE / 4)
            cp16(Pn + tid * 4, g_blob + (size_t)(r + 1) * RSTRIDE + tid * 4);
        asm volatile("cp.async.commit_group;\n");

        const int tgt = ((const int*)P)[1568 + wid];
        if (tgt >= 0) {
            const uint2* s2 = (const uint2*)((const unsigned*)P + wid * 16);
            const float* ww = P + 512 + wid * 32;
            const float  bt = P[1536 + wid];

            float a0 = 0.f, a1 = 0.f, a2 = 0.f, a3 = 0.f;   // chain A, 4 cols
            float b4 = 0.f, b5 = 0.f, b6 = 0.f, b7 = 0.f;   // chain B, 4 cols
            #pragma unroll
            for (int q = 0; q < 8; q++) {
                uint2  u  = s2[q];                 // 4 src offsets (uniform LDS)
                float4 w4 = *(const float4*)(ww + 4 * q);
                uint2 h0 = *(const uint2*)(stc + (u.x & 0xFFFFu));
                uint2 h1 = *(const uint2*)(stc + (u.x >> 16));
                uint2 h2 = *(const uint2*)(stc + (u.y & 0xFFFFu));
                uint2 h3 = *(const uint2*)(stc + (u.y >> 16));
                float2 p0a = __half22float2(*(__half2*)&h0.x);
                float2 p0b = __half22float2(*(__half2*)&h0.y);
                float2 p1a = __half22float2(*(__half2*)&h1.x);
                float2 p1b = __half22float2(*(__half2*)&h1.y);
                float2 p2a = __half22float2(*(__half2*)&h2.x);
                float2 p2b = __half22float2(*(__half2*)&h2.y);
                float2 p3a = __half22float2(*(__half2*)&h3.x);
                float2 p3b = __half22float2(*(__half2*)&h3.y);
                a0 = fmaf(p0a.x, w4.x, a0);  a1 = fmaf(p0a.y, w4.x, a1);
                a2 = fmaf(p0b.x, w4.x, a2);  a3 = fmaf(p0b.y, w4.x, a3);
                b4 = fmaf(p1a.x, w4.y, b4);  b5 = fmaf(p1a.y, w4.y, b5);
                b6 = fmaf(p1b.x, w4.y, b6);  b7 = fmaf(p1b.y, w4.y, b7);
                a0 = fmaf(p2a.x, w4.z, a0);  a1 = fmaf(p2a.y, w4.z, a1);
                a2 = fmaf(p2b.x, w4.z, a2);  a3 = fmaf(p2b.y, w4.z, a3);
                b4 = fmaf(p3a.x, w4.w, b4);  b5 = fmaf(p3a.y, w4.w, b5);
                b6 = fmaf(p3b.x, w4.w, b6);  b7 = fmaf(p3b.y, w4.w, b7);
            }
            float z0 = (a0 + b4) + bt;
            float z1 = (a1 + b5) + bt;
            float z2 = (a2 + b6) + bt;
            float z3 = (a3 + b7) + bt;
            float o0 = __fdividef(1.0f, 1.0f + __expf(-z0));
            float o1 = __fdividef(1.0f, 1.0f + __expf(-z1));
            float o2 = __fdividef(1.0f, 1.0f + __expf(-z2));
            float o3 = __fdividef(1.0f, 1.0f + __expf(-z3));
            __half2 ha = __floats2half2_rn(o0, o1);
            __half2 hb = __floats2half2_rn(o2, o3);
            uint2 pk;
            pk.x = *(uint32_t*)&ha;
            pk.y = *(uint32_t*)&hb;
            *(uint2*)(stc + tgt) = pk;
        }

        asm volatile("cp.async.wait_group 0;\n" ::: "memory");
        __syncthreads();
    }

    // ---- output: out[b][j] f32; 4 chunks of 16 output nodes ----
    for (int ch = 0; ch < 4; ch++) {
        const int j0 = ch * 16;
        __syncthreads();
        {
            int j = tid >> 6, wc = tid & 63;       // 1024 = 16 j x 64 words
            uint32_t u = st[(NUM_IN + NUM_HID + j0 + j) * WPN + wc];
            float2 v = __half22float2(*(__half2*)&u);
            stage[(2 * wc) * 17 + j]     = v.x;
            stage[(2 * wc + 1) * 17 + j] = v.y;
        }
        __syncthreads();
        #pragma unroll
        for (int i = 0; i < 2; i++) {
            int idx = tid + i * THREADS;           // 2048 = 128 rows x 16 j
            int row = idx >> 4, j = idx & 15;
            out[(size_t)(b0 + row) * NUM_OUT + j0 + j] = stage[row * 17 + j];
        }
    }
}

// ---------------------------------------------------------------------------
extern "C" void kernel_launch(void* const* d_in, const int* in_sizes, int n_in,
                              void* d_out, int out_size) {
    const float* x    = (const float*)d_in[0];
    const float* w    = (const float*)d_in[1];
    const float* bias = (const float*)d_in[2];
    const int*   src  = (const int*)d_in[3];
    float* out = (float*)d_out;
    (void)in_sizes; (void)n_in; (void)out_size;

    cudaFuncSetAttribute(neat_main_kernel,
                         cudaFuncAttributeMaxDynamicSharedMemorySize,
                         TOTAL_WORDS * 4);

    schedule_kernel<<<1, M_NODES>>>(src);
    blob_fill_kernel<<<RMAX, 256>>>(src, w, bias);
    neat_main_kernel<<<BATCH / COLS, THREADS, TOTAL_WORDS * 4>>>(x, out);
}

// round 9
// speedup vs baseline: 1.2333x; 1.0375x over previous
#include <cuda_runtime.h>
#include <cstdint>

#define BATCH   32768
#define NUM_IN  256
#define NUM_HID 512
#define NUM_OUT 64
#define M_NODES 576
#define N_NODES 832
#define KFAN    32
#define COLS    64             // batch columns per block (fp32)
#define WPN     64             // f32 words per node row
#define THREADS 512            // 16 warps
#define CAP     40             // max nodes per round (level split capacity)
#define NSTRIDE 52             // words per node in blob: 32 w + 16 src16 + bias + tgt + 2 pad
#define RSTRIDE (CAP * NSTRIDE)   // 2080 words per round
#define RMAX_R  576            // absolute worst-case rounds

// blob: round-major, node-sub-major. node slot i of round r at r*RSTRIDE + i*52:
//   [0..32) w, [32..48) src16 (two u16 pred*WPN offsets per u32), [48] bias,
//   [49] target word-offset (int), [50..52) pad
__device__ float g_blob[(size_t)RMAX_R * RSTRIDE];
__device__ int   g_sched[RMAX_R * CAP];
__device__ int   g_rcnt[RMAX_R];
__device__ int   g_nrounds;

// ---------------------------------------------------------------------------
// Kernel A: ASAP levels — 18 chunks of 32 nodes, one warp per chunk,
// intra-chunk convergence via ballot only; 18 block barriers total.
// Then counting-sort levels into rounds of <= CAP nodes.
// ---------------------------------------------------------------------------
__global__ __launch_bounds__(M_NODES)
void schedule_kernel(const int* __restrict__ src) {
    __shared__ int lev_n[N_NODES];                 // node-space levels (inputs = 0)
    __shared__ int cnt[M_NODES + 1];
    __shared__ int lbase[M_NODES + 1];             // first round of level L
    __shared__ int pos[M_NODES + 1];
    __shared__ int lmax;

    const int t   = threadIdx.x;
    const int wid = t >> 5;

    int p[KFAN];                                   // preds in node space
    #pragma unroll
    for (int k = 0; k < KFAN; k++) p[k] = src[t * KFAN + k];

    for (int i = t; i < N_NODES; i += M_NODES) lev_n[i] = 0;
    if (t + M_NODES < N_NODES) lev_n[t + M_NODES] = 0;   // covers 832 (576+256)
    for (int i = t; i <= M_NODES; i += M_NODES) { cnt[i] = 0; pos[i] = 0; }
    if (t == 0) lmax = 0;
    __syncthreads();

    int myl = 0;
    for (int c = 0; c < M_NODES / 32; c++) {       // 18 chunks, ascending
        if (wid == c) {
            bool ch = true;
            while (__ballot_sync(0xFFFFFFFFu, ch)) {
                int m = 0;
                #pragma unroll
                for (int k = 0; k < KFAN; k++) {
                    int l = lev_n[p[k]];
                    m = (l > m) ? l : m;
                }
                ch = (m + 1 != myl);
                if (ch) { myl = m + 1; lev_n[NUM_IN + t] = myl; }
                __syncwarp();
            }
        }
        __syncthreads();
    }

    atomicAdd(&cnt[myl], 1);
    atomicMax(&lmax, myl);
    __syncthreads();

    if (t == 0) {
        int R = 0;
        for (int L = 1; L <= lmax; L++) {
            lbase[L] = R;
            int wL = cnt[L];
            while (wL > 0) {                       // split wide levels
                g_rcnt[R] = (wL < CAP) ? wL : CAP;
                wL -= CAP;
                R++;
            }
        }
        g_nrounds = R;
    }
    __syncthreads();

    {   // slot assignment (any order within a level is valid)
        int q = atomicAdd(&pos[myl], 1);
        int r = lbase[myl] + q / CAP;
        g_sched[r * CAP + (q % CAP)] = t;
    }
}

// ---------------------------------------------------------------------------
// Kernel B: blob fill — one block per round, 64 threads.
// ---------------------------------------------------------------------------
__global__ __launch_bounds__(64)
void blob_fill_kernel(const int* __restrict__ src,
                      const float* __restrict__ w,
                      const float* __restrict__ bias) {
    const int r = blockIdx.x;
    if (r >= g_nrounds) return;
    const int rc = g_rcnt[r];
    float* Pr = g_blob + (size_t)r * RSTRIDE;
    const int tid = threadIdx.x;

    for (int s = 0; s < rc; s++) {
        const int nd = g_sched[r * CAP + s];
        float* Pn = Pr + s * NSTRIDE;
        if (tid < 32) {
            Pn[tid] = w[nd * KFAN + tid];
        } else if (tid < 48) {
            int j = tid - 32;
            unsigned a = (unsigned)src[nd * KFAN + 2 * j] * WPN;
            unsigned b = (unsigned)src[nd * KFAN + 2 * j + 1] * WPN;
            ((unsigned*)Pn)[32 + j] = (a & 0xFFFFu) | (b << 16);
        } else if (tid == 48) {
            Pn[48] = bias[nd];
        } else if (tid == 49) {
            ((int*)Pn)[49] = (NUM_IN + nd) * WPN;
        }
    }
}

// ---------------------------------------------------------------------------
// Main kernel: 512 blocks x 512 threads, 1 block/SM. fp32 state in SMEM,
// variable-width rounds (one barrier per DAG level / capacity split),
// warp w handles node slots w, w+16, ... of each round.
// ---------------------------------------------------------------------------
#define ST_WORDS    (N_NODES * WPN)                // 53248
#define PBUF_WORDS  (2 * RSTRIDE)                  // 4160 (also input staging 2112)
#define RCNT_WORDS  RMAX_R                         // 576
#define TOTAL_WORDS (ST_WORDS + PBUF_WORDS + RCNT_WORDS)   // 57984 -> 231936 B

extern __shared__ float smem_f[];

__device__ __forceinline__ void cp16(void* sdst, const void* gsrc) {
    uint32_t s = (uint32_t)__cvta_generic_to_shared(sdst);
    asm volatile("cp.async.cg.shared.global [%0], [%1], 16;\n" :: "r"(s), "l"(gsrc));
}

__global__ __launch_bounds__(THREADS, 1)
void neat_main_kernel(const float* __restrict__ x,
                      float* __restrict__ out) {
    float* st    = smem_f;                         // [N_NODES][WPN]
    float* stage = smem_f + ST_WORDS;              // param double buf / staging
    int*   srcnt = (int*)(smem_f + ST_WORDS + PBUF_WORDS);

    const int tid  = threadIdx.x;
    const int wid  = tid >> 5;
    const int lane = tid & 31;
    const int b0   = blockIdx.x * COLS;
    const int R    = g_nrounds;

    // ---- round headers into smem ----
    for (int i = tid; i < R; i += THREADS) srcnt[i] = g_rcnt[i];

    // ---- input transpose: x[b][n] -> st[n][col]; 8 chunks of 32 inputs ----
    for (int ch = 0; ch < 8; ch++) {
        const int nc0 = ch * 32;
        __syncthreads();
        #pragma unroll
        for (int i = 0; i < 4; i++) {
            int idx = tid + i * THREADS;           // 2048 = 64 rows x 32 cols
            int row = idx >> 5, c = idx & 31;
            stage[row * 33 + c] = x[(size_t)(b0 + row) * NUM_IN + nc0 + c];
        }
        __syncthreads();
        #pragma unroll
        for (int i = 0; i < 4; i++) {
            int idx = tid + i * THREADS;           // 2048 = 32 nodes x 64 cols
            int n = idx >> 6, col = idx & 63;
            st[(nc0 + n) * WPN + col] = stage[col * 33 + n];
        }
    }
    __syncthreads();

    // ---- prefetch round 0 params (2080 words = 520 x 16B) ----
    if (tid < RSTRIDE / 4) cp16(stage + tid * 4, g_blob + tid * 4);
    asm volatile("cp.async.commit_group;\n");
    asm volatile("cp.async.wait_group 0;\n" ::: "memory");
    __syncthreads();

    float* stc = st + 2 * lane;                    // lane owns cols (2l, 2l+1)

    // ---- main rounds ----
    for (int r = 0; r < R; r++) {
        float* P  = stage + (r & 1) * RSTRIDE;
        float* Pn = stage + ((r + 1) & 1) * RSTRIDE;
        if (r + 1 < R && tid < RSTRIDE / 4)
            cp16(Pn + tid * 4, g_blob + (size_t)(r + 1) * RSTRIDE + tid * 4);
        asm volatile("cp.async.commit_group;\n");

        const int rc = srcnt[r];
        for (int s = wid; s < rc; s += 16) {
            const float* Pp = P + s * NSTRIDE;
            const uint2* sp = (const uint2*)((const unsigned*)Pp + 32);
            const float4* wp = (const float4*)Pp;
            const float  bt = Pp[48];
            const int    tgt = ((const int*)Pp)[49];

            float a0 = 0.f, a1 = 0.f, b0a = 0.f, b1a = 0.f;
            #pragma unroll
            for (int q = 0; q < 8; q++) {
                uint2  u  = sp[q];                 // 4 offsets (uniform LDS.64)
                float4 w4 = wp[q];                 // 4 weights (uniform LDS.128)
                float2 v0 = *(const float2*)(stc + (u.x & 0xFFFFu));
                float2 v1 = *(const float2*)(stc + (u.x >> 16));
                float2 v2 = *(const float2*)(stc + (u.y & 0xFFFFu));
                float2 v3 = *(const float2*)(stc + (u.y >> 16));
                a0  = fmaf(v0.x, w4.x, a0);  a1  = fmaf(v0.y, w4.x, a1);
                b0a = fmaf(v1.x, w4.y, b0a); b1a = fmaf(v1.y, w4.y, b1a);
                a0  = fmaf(v2.x, w4.z, a0);  a1  = fmaf(v2.y, w4.z, a1);
                b0a = fmaf(v3.x, w4.w, b0a); b1a = fmaf(v3.y, w4.w, b1a);
            }
            float z0 = (a0 + b0a) + bt;
            float z1 = (a1 + b1a) + bt;
            float o0 = __fdividef(1.0f, 1.0f + __expf(-z0));
            float o1 = __fdividef(1.0f, 1.0f + __expf(-z1));
            *(float2*)(stc + tgt) = make_float2(o0, o1);
        }

        asm volatile("cp.async.wait_group 0;\n" ::: "memory");
        __syncthreads();
    }

    // ---- output: out[b][j] = st[768+j][col]; 2 chunks of 32 outputs ----
    for (int ch = 0; ch < 2; ch++) {
        const int j0 = ch * 32;
        __syncthreads();
        #pragma unroll
        for (int i = 0; i < 4; i++) {
            int idx = tid + i * THREADS;           // 2048 = 32 j x 64 cols
            int j = idx >> 6, col = idx & 63;
            stage[col * 33 + j] = st[(NUM_IN + NUM_HID + j0 + j) * WPN + col];
        }
        __syncthreads();
        #pragma unroll
        for (int i = 0; i < 4; i++) {
            int idx = tid + i * THREADS;           // 2048 = 64 rows x 32 j
            int row = idx >> 5, j = idx & 31;
            out[(size_t)(b0 + row) * NUM_OUT + j0 + j] = stage[row * 33 + j];
        }
    }
}

// ---------------------------------------------------------------------------
extern "C" void kernel_launch(void* const* d_in, const int* in_sizes, int n_in,
                              void* d_out, int out_size) {
    const float* x    = (const float*)d_in[0];
    const float* w    = (const float*)d_in[1];
    const float* bias = (const float*)d_in[2];
    const int*   src  = (const int*)d_in[3];
    float* out = (float*)d_out;
    (void)in_sizes; (void)n_in; (void)out_size;

    cudaFuncSetAttribute(neat_main_kernel,
                         cudaFuncAttributeMaxDynamicSharedMemorySize,
                         TOTAL_WORDS * 4);

    schedule_kernel<<<1, M_NODES>>>(src);
    blob_fill_kernel<<<RMAX_R, 64>>>(src, w, bias);
    neat_main_kernel<<<BATCH / COLS, THREADS, TOTAL_WORDS * 4>>>(x, out);
}